// round 3
// baseline (speedup 1.0000x reference)
#include <cuda_runtime.h>

#define BB 8
#define LL 1024
#define DD 512
#define HD 4096

// Accumulators with contention-spreading copies (device globals)
__device__ float g_xsum2[2][BB * DD];     // 2 copies, 32 KB
__device__ float g_vsum4[4][BB * HD];     // 4 copies, 512 KB
__device__ float g_zc  [8][BB * DD];      // 8 copies, 128 KB
__device__ float g_z      [BB * DD];      // final z, 16 KB

// K0: init copies. copy0 gets the bias terms, others zero.
// Largest region: 3*BB*HD = 98304 -> grid 96 x 1024.
__global__ void k0_init(const float* __restrict__ bv, const float* __restrict__ fcb) {
    int i = blockIdx.x * 1024 + threadIdx.x;
    if (i < 2 * BB * DD) (&g_xsum2[0][0])[i] = 0.f;
    if (i < BB * HD)     g_vsum4[0][i] = (float)LL * bv[i & (HD - 1)];
    if (i < 3 * BB * HD) (&g_vsum4[1][0])[i] = 0.f;
    if (i < BB * DD)     g_zc[0][i] = fcb[i & (DD - 1)];
    if (i < 7 * BB * DD) (&g_zc[1][0])[i] = 0.f;
}

// K1: xsum += sum over 32 L-rows. grid (8 b, 32 c), 128 threads.
// Each thread sums its float4 column over 32 rows (32 LDG.128 in flight).
__global__ void k1_sumL(const float* __restrict__ x) {
    int b = blockIdx.x, c = blockIdx.y, t = threadIdx.x;
    const float4* p = reinterpret_cast<const float4*>(x)
                    + (size_t)b * LL * (DD / 4) + (size_t)c * 32 * (DD / 4) + t;
    float4 s = make_float4(0.f, 0.f, 0.f, 0.f);
#pragma unroll
    for (int r = 0; r < 32; ++r) {
        float4 v = p[r * (DD / 4)];
        s.x += v.x; s.y += v.y; s.z += v.z; s.w += v.w;
    }
    float* dst = &g_xsum2[c & 1][b * DD + 4 * t];
    atomicAdd(dst + 0, s.x); atomicAdd(dst + 1, s.y);
    atomicAdd(dst + 2, s.z); atomicAdd(dst + 3, s.w);
}

// K2: vsum += xsum @ wv. grid (jb=8, kc=32), 128 threads.
// Block: j in [jb*512, jb*512+512), k in [kc*16, kc*16+16).
// Thread t owns j-quad jb*512 + 4t; 16 LDG.128 of wv per thread.
__global__ void k2_vsum(const float* __restrict__ wv) {
    __shared__ float xs[BB * 16];     // xsum chunk (both copies merged)
    int t = threadIdx.x;
    int jb = blockIdx.x, kc = blockIdx.y;
    int k0 = kc * 16;
    {   // 128 entries, 128 threads
        int b = t >> 4, kk = t & 15;
        int a = b * DD + k0 + kk;
        xs[t] = g_xsum2[0][a] + g_xsum2[1][a];
    }
    __syncthreads();

    float4 acc[BB];
#pragma unroll
    for (int b = 0; b < BB; ++b) acc[b] = make_float4(0.f, 0.f, 0.f, 0.f);

    const float4* w = reinterpret_cast<const float4*>(wv)
                    + (size_t)k0 * (HD / 4) + jb * 128 + t;
#pragma unroll
    for (int kk = 0; kk < 16; ++kk) {
        float4 wv4 = w[kk * (HD / 4)];
#pragma unroll
        for (int b = 0; b < BB; ++b) {
            float xv = xs[b * 16 + kk];
            acc[b].x += xv * wv4.x; acc[b].y += xv * wv4.y;
            acc[b].z += xv * wv4.z; acc[b].w += xv * wv4.w;
        }
    }
    int j = jb * 512 + 4 * t;
    float* base = &g_vsum4[kc & 3][0];
#pragma unroll
    for (int b = 0; b < BB; ++b) {
        float* dst = base + b * HD + j;
        atomicAdd(dst + 0, acc[b].x); atomicAdd(dst + 1, acc[b].y);
        atomicAdd(dst + 2, acc[b].z); atomicAdd(dst + 3, acc[b].w);
    }
}

// K3: zc += vsum @ fc_w. grid 256 (j-chunks of 16), 128 threads.
// Thread t owns i-quad 4t; 16 LDG.128 of fc_w per thread.
__global__ void k3_z(const float* __restrict__ fcw) {
    __shared__ float vs[BB * 16];
    int t = threadIdx.x;
    int jc = blockIdx.x;
    int j0 = jc * 16;
    {   // 128 entries: merge the 4 vsum copies
        int b = t >> 4, jj = t & 15;
        int a = b * HD + j0 + jj;
        vs[t] = g_vsum4[0][a] + g_vsum4[1][a] + g_vsum4[2][a] + g_vsum4[3][a];
    }
    __syncthreads();

    float4 acc[BB];
#pragma unroll
    for (int b = 0; b < BB; ++b) acc[b] = make_float4(0.f, 0.f, 0.f, 0.f);

    const float4* w = reinterpret_cast<const float4*>(fcw)
                    + (size_t)j0 * (DD / 4) + t;
#pragma unroll
    for (int jj = 0; jj < 16; ++jj) {
        float4 wv4 = w[jj * (DD / 4)];
#pragma unroll
        for (int b = 0; b < BB; ++b) {
            float vv = vs[b * 16 + jj];
            acc[b].x += vv * wv4.x; acc[b].y += vv * wv4.y;
            acc[b].z += vv * wv4.z; acc[b].w += vv * wv4.w;
        }
    }
    float* base = &g_zc[jc & 7][0];
#pragma unroll
    for (int b = 0; b < BB; ++b) {
        float* dst = base + b * DD + 4 * t;
        atomicAdd(dst + 0, acc[b].x); atomicAdd(dst + 1, acc[b].y);
        atomicAdd(dst + 2, acc[b].z); atomicAdd(dst + 3, acc[b].w);
    }
}

// K3b: merge the 8 z copies. 4096 elements.
__global__ void k3b_merge() {
    int i = blockIdx.x * 1024 + threadIdx.x;
    if (i < BB * DD) {
        float s = 0.f;
#pragma unroll
        for (int c = 0; c < 8; ++c) s += g_zc[c][i];
        g_z[i] = s;
    }
}

// K4: out = LayerNorm(z[b] + x[b,l]) * g + beta. Warp-per-row.
__global__ void k4_ln(const float* __restrict__ x,
                      const float* __restrict__ lng, const float* __restrict__ lnb,
                      float* __restrict__ out) {
    int warp = (blockIdx.x * blockDim.x + threadIdx.x) >> 5;  // row 0..8191
    int lane = threadIdx.x & 31;
    int b = warp >> 10;

    const float4* xp = reinterpret_cast<const float4*>(x) + (size_t)warp * 128;
    const float4* zp = reinterpret_cast<const float4*>(g_z) + b * 128;

    float4 y[4];
    float s = 0.f, q = 0.f;
#pragma unroll
    for (int i = 0; i < 4; ++i) {
        float4 xv = xp[lane + 32 * i];
        float4 zv = zp[lane + 32 * i];
        y[i].x = xv.x + zv.x; y[i].y = xv.y + zv.y;
        y[i].z = xv.z + zv.z; y[i].w = xv.w + zv.w;
        s += y[i].x + y[i].y + y[i].z + y[i].w;
        q += y[i].x * y[i].x + y[i].y * y[i].y + y[i].z * y[i].z + y[i].w * y[i].w;
    }
#pragma unroll
    for (int o = 16; o > 0; o >>= 1) {
        s += __shfl_xor_sync(0xFFFFFFFFu, s, o);
        q += __shfl_xor_sync(0xFFFFFFFFu, q, o);
    }
    float mu  = s * (1.0f / DD);
    float var = q * (1.0f / DD) - mu * mu;
    float inv = rsqrtf(var + 1e-5f);

    const float4* gp = reinterpret_cast<const float4*>(lng);
    const float4* bp = reinterpret_cast<const float4*>(lnb);
    float4* op = reinterpret_cast<float4*>(out) + (size_t)warp * 128;
#pragma unroll
    for (int i = 0; i < 4; ++i) {
        float4 gv = gp[lane + 32 * i];
        float4 be = bp[lane + 32 * i];
        float4 o;
        o.x = (y[i].x - mu) * inv * gv.x + be.x;
        o.y = (y[i].y - mu) * inv * gv.y + be.y;
        o.z = (y[i].z - mu) * inv * gv.z + be.z;
        o.w = (y[i].w - mu) * inv * gv.w + be.w;
        op[lane + 32 * i] = o;
    }
}

extern "C" void kernel_launch(void* const* d_in, const int* in_sizes, int n_in,
                              void* d_out, int out_size) {
    const float* input = (const float*)d_in[0];
    const float* wv    = (const float*)d_in[5];
    const float* bv    = (const float*)d_in[6];
    const float* fcw   = (const float*)d_in[9];
    const float* fcb   = (const float*)d_in[10];
    const float* lng   = (const float*)d_in[11];
    const float* lnb   = (const float*)d_in[12];
    float* out = (float*)d_out;

    k0_init  <<<96, 1024>>>(bv, fcb);
    k1_sumL  <<<dim3(BB, 32), 128>>>(input);
    k2_vsum  <<<dim3(8, 32), 128>>>(wv);
    k3_z     <<<256, 128>>>(fcw);
    k3b_merge<<<4, 1024>>>();
    k4_ln    <<<BB * LL / 8, 256>>>(input, lng, lnb, out);
}

// round 4
// speedup vs baseline: 1.2605x; 1.2605x over previous
#include <cuda_runtime.h>

#define BB 8
#define LL 1024
#define DD 512
#define HD 4096
#define NZC 16    // z accumulator copies

// Accumulators (device globals; 16B-aligned for red.v4)
__device__ __align__(16) float g_xsum2[2][BB * DD];      // 32 KB
__device__ __align__(16) float g_vsum4[4][BB * HD];      // 512 KB
__device__ __align__(16) float g_zc[NZC][BB * DD];       // 256 KB

// Fire-and-forget vector reduction (sm_90+)
__device__ __forceinline__ void red_add_v4(float* addr, float4 v) {
    asm volatile("red.global.add.v4.f32 [%0], {%1,%2,%3,%4};"
                 :: "l"(addr), "f"(v.x), "f"(v.y), "f"(v.z), "f"(v.w)
                 : "memory");
}

// K0: init accumulators. xsum2=0; vsum4[0]=L*bv, rest 0; zc[0]=fcb, rest 0.
// Largest region 3*BB*HD=98304 -> 96 blocks x 1024.
__global__ void k0_init(const float* __restrict__ bv, const float* __restrict__ fcb) {
    int i = blockIdx.x * 1024 + threadIdx.x;
    if (i < 2 * BB * DD)          (&g_xsum2[0][0])[i] = 0.f;
    if (i < BB * HD)              g_vsum4[0][i] = (float)LL * bv[i & (HD - 1)];
    if (i < 3 * BB * HD)          (&g_vsum4[1][0])[i] = 0.f;
    if (i < BB * DD)              g_zc[0][i] = fcb[i & (DD - 1)];
    if (i < (NZC - 1) * BB * DD)  (&g_zc[1][0])[i] = 0.f;
}

// K1: xsum += sum over 16 L-rows. grid (8 b, 64 c) = 512 blocks, 128 threads.
// Thread owns one float4 column; 16 independent LDG.128; one v4-red.
__global__ void k1_sumL(const float* __restrict__ x) {
    int b = blockIdx.x, c = blockIdx.y, t = threadIdx.x;
    const float4* p = reinterpret_cast<const float4*>(x)
                    + (size_t)b * LL * 128 + (size_t)c * 16 * 128 + t;
    float4 s = make_float4(0.f, 0.f, 0.f, 0.f);
#pragma unroll
    for (int r = 0; r < 16; ++r) {
        float4 v = p[r * 128];
        s.x += v.x; s.y += v.y; s.z += v.z; s.w += v.w;
    }
    red_add_v4(&g_xsum2[c & 1][b * DD + 4 * t], s);
}

// K2: vsum += xsum @ wv.  wv is [DD x HD] row-major.
// Tile: 8 k-rows x 512 j-cols (16 KB) staged in smem.
// grid (jb=8, kc=64) = 512 blocks, 256 threads (8 warps).
__global__ void k2_vsum(const float* __restrict__ wv) {
    __shared__ float4 sw[8 * 128];     // sw[kk*128 + jq], 16 KB
    __shared__ float  xs[BB * 8];      // xsum chunk merged from 2 copies
    int t = threadIdx.x;
    int jb = blockIdx.x, kc = blockIdx.y;
    int k0 = kc * 8;

    // stage weights: 1024 quads / 256 threads = 4 LDG.128 each
    const float4* w4 = reinterpret_cast<const float4*>(wv);
#pragma unroll
    for (int u = 0; u < 4; ++u) {
        int g = t + u * 256;           // 0..1023
        int kk = g >> 7, jq = g & 127;
        sw[g] = w4[(size_t)(k0 + kk) * (HD / 4) + jb * 128 + jq];
    }
    if (t < BB * 8) {
        int b = t >> 3, kk = t & 7;
        int a = b * DD + k0 + kk;
        xs[t] = g_xsum2[0][a] + g_xsum2[1][a];
    }
    __syncthreads();

    int jq = t & 127, bg = t >> 7;     // bg in {0,1}: 4 b's each
    float4 acc[4];
#pragma unroll
    for (int i = 0; i < 4; ++i) acc[i] = make_float4(0.f, 0.f, 0.f, 0.f);
#pragma unroll
    for (int kk = 0; kk < 8; ++kk) {
        float4 wq = sw[kk * 128 + jq];
#pragma unroll
        for (int bi = 0; bi < 4; ++bi) {
            float xv = xs[(bg * 4 + bi) * 8 + kk];
            acc[bi].x += xv * wq.x; acc[bi].y += xv * wq.y;
            acc[bi].z += xv * wq.z; acc[bi].w += xv * wq.w;
        }
    }
    float* base = &g_vsum4[kc & 3][0];
#pragma unroll
    for (int bi = 0; bi < 4; ++bi)
        red_add_v4(base + (bg * 4 + bi) * HD + jb * 512 + jq * 4, acc[bi]);
}

// K3: zc += vsum @ fc_w.  fc_w is [HD x DD] row-major.
// Tile: 8 j-rows x all 512 i (16 KB) staged in smem.
// grid 512 blocks (j-chunks of 8), 256 threads.
__global__ void k3_z(const float* __restrict__ fcw) {
    __shared__ float4 sw[8 * 128];     // sw[jj*128 + iq], 16 KB
    __shared__ float  vs[BB * 8];      // vsum chunk merged from 4 copies
    int t = threadIdx.x;
    int jc = blockIdx.x;
    int j0 = jc * 8;

    const float4* w4 = reinterpret_cast<const float4*>(fcw);
#pragma unroll
    for (int u = 0; u < 4; ++u) {
        int g = t + u * 256;
        int jj = g >> 7, iq = g & 127;
        sw[g] = w4[(size_t)(j0 + jj) * (DD / 4) + iq];
    }
    if (t < BB * 8) {
        int b = t >> 3, jj = t & 7;
        int a = b * HD + j0 + jj;
        vs[t] = g_vsum4[0][a] + g_vsum4[1][a] + g_vsum4[2][a] + g_vsum4[3][a];
    }
    __syncthreads();

    int iq = t & 127, bg = t >> 7;
    float4 acc[4];
#pragma unroll
    for (int i = 0; i < 4; ++i) acc[i] = make_float4(0.f, 0.f, 0.f, 0.f);
#pragma unroll
    for (int jj = 0; jj < 8; ++jj) {
        float4 wq = sw[jj * 128 + iq];
#pragma unroll
        for (int bi = 0; bi < 4; ++bi) {
            float vv = vs[(bg * 4 + bi) * 8 + jj];
            acc[bi].x += vv * wq.x; acc[bi].y += vv * wq.y;
            acc[bi].z += vv * wq.z; acc[bi].w += vv * wq.w;
        }
    }
    float* base = &g_zc[jc & (NZC - 1)][0];
#pragma unroll
    for (int bi = 0; bi < 4; ++bi)
        red_add_v4(base + (bg * 4 + bi) * DD + iq * 4, acc[bi]);
}

// K4: out = LayerNorm(merge(zc)[b] + x[b,l]) * g + beta.
// 1024 blocks x 256 threads; block = 8 rows (same b). First 128 threads merge
// the 16 zc copies into smem, then warp-per-row LN with xor-shuffle reduce.
__global__ void k4_ln(const float* __restrict__ x,
                      const float* __restrict__ lng, const float* __restrict__ lnb,
                      float* __restrict__ out) {
    __shared__ float4 zs[128];         // merged z row for this b (2 KB)
    int t = threadIdx.x;
    int row0 = blockIdx.x * 8;
    int b = blockIdx.x >> 7;           // 128 blocks per batch

    if (t < 128) {
        float4 s = make_float4(0.f, 0.f, 0.f, 0.f);
#pragma unroll
        for (int c = 0; c < NZC; ++c) {
            float4 v = reinterpret_cast<const float4*>(&g_zc[c][0])[b * 128 + t];
            s.x += v.x; s.y += v.y; s.z += v.z; s.w += v.w;
        }
        zs[t] = s;
    }
    __syncthreads();

    int warp = t >> 5, lane = t & 31;
    int row = row0 + warp;

    const float4* xp = reinterpret_cast<const float4*>(x) + (size_t)row * 128;
    float4 y[4];
    float s = 0.f, q = 0.f;
#pragma unroll
    for (int i = 0; i < 4; ++i) {
        float4 xv = xp[lane + 32 * i];
        float4 zv = zs[lane + 32 * i];
        y[i].x = xv.x + zv.x; y[i].y = xv.y + zv.y;
        y[i].z = xv.z + zv.z; y[i].w = xv.w + zv.w;
        s += y[i].x + y[i].y + y[i].z + y[i].w;
        q += y[i].x * y[i].x + y[i].y * y[i].y + y[i].z * y[i].z + y[i].w * y[i].w;
    }
#pragma unroll
    for (int o = 16; o > 0; o >>= 1) {
        s += __shfl_xor_sync(0xFFFFFFFFu, s, o);
        q += __shfl_xor_sync(0xFFFFFFFFu, q, o);
    }
    float mu  = s * (1.0f / DD);
    float var = q * (1.0f / DD) - mu * mu;
    float inv = rsqrtf(var + 1e-5f);

    const float4* gp = reinterpret_cast<const float4*>(lng);
    const float4* bp = reinterpret_cast<const float4*>(lnb);
    float4* op = reinterpret_cast<float4*>(out) + (size_t)row * 128;
#pragma unroll
    for (int i = 0; i < 4; ++i) {
        float4 gv = gp[lane + 32 * i];
        float4 be = bp[lane + 32 * i];
        float4 o;
        o.x = (y[i].x - mu) * inv * gv.x + be.x;
        o.y = (y[i].y - mu) * inv * gv.y + be.y;
        o.z = (y[i].z - mu) * inv * gv.z + be.z;
        o.w = (y[i].w - mu) * inv * gv.w + be.w;
        op[lane + 32 * i] = o;
    }
}

extern "C" void kernel_launch(void* const* d_in, const int* in_sizes, int n_in,
                              void* d_out, int out_size) {
    const float* input = (const float*)d_in[0];
    const float* wv    = (const float*)d_in[5];
    const float* bv    = (const float*)d_in[6];
    const float* fcw   = (const float*)d_in[9];
    const float* fcb   = (const float*)d_in[10];
    const float* lng   = (const float*)d_in[11];
    const float* lnb   = (const float*)d_in[12];
    float* out = (float*)d_out;

    k0_init<<<96, 1024>>>(bv, fcb);
    k1_sumL<<<dim3(BB, 64), 128>>>(input);
    k2_vsum<<<dim3(8, 64), 256>>>(wv);
    k3_z   <<<512, 256>>>(fcw);
    k4_ln  <<<BB * LL / 8, 256>>>(input, lng, lnb, out);
}

// round 5
// speedup vs baseline: 1.4000x; 1.1106x over previous
#include <cuda_runtime.h>

#define BB 8
#define LL 1024
#define DD 512
#define HD 4096

// Accumulators. Statics are zero-initialized at module load (first call OK);
// k4's epilogue re-zeroes xsum2/vsum4 for the next graph replay; zc is
// re-initialized by kA's extra blocks every call.
__device__ __align__(16) float g_xsum2[2][BB * DD];   // 32 KB
__device__ __align__(16) float g_vsum4[4][BB * HD];   // 512 KB
__device__ __align__(16) float g_zc[8][BB * DD];      // 128 KB

__device__ __forceinline__ void red_add_v4(float* a, float4 v) {
    asm volatile("red.global.add.v4.f32 [%0], {%1,%2,%3,%4};"
                 :: "l"(a), "f"(v.x), "f"(v.y), "f"(v.z), "f"(v.w) : "memory");
}

// kA: blocks [0,256): xsum += input summed over L (red into 2 copies).
//     blocks [256,288): zero g_zc for this call.
__global__ void kA(const float* __restrict__ x) {
    int blk = blockIdx.x, t = threadIdx.x;
    if (blk >= 256) {
        int q = (blk - 256) * 256 + t;   // 8192 quads total
        reinterpret_cast<float4*>(&g_zc[0][0])[q] = make_float4(0.f, 0.f, 0.f, 0.f);
        return;
    }
    int b = blk >> 5, c = blk & 31;          // 32 L-chunks of 32 rows
    int h = t >> 7, q = t & 127;             // row-half, quad
    const float4* p = reinterpret_cast<const float4*>(x)
                    + (size_t)b * LL * 128 + (size_t)(c * 32 + h * 16) * 128 + q;
    float4 s = make_float4(0.f, 0.f, 0.f, 0.f);
#pragma unroll
    for (int r = 0; r < 16; ++r) {
        float4 v = p[r * 128];
        s.x += v.x; s.y += v.y; s.z += v.z; s.w += v.w;
    }
    red_add_v4(&g_xsum2[h][b * DD + 4 * q], s);
}

// k2: vsum += xsum @ wv (+ L*bv on kc==0).  wv is [DD x HD] row-major.
// grid (jb=8, kc=32), 512 threads. Tile: 16 k-rows x 512 j (32 KB).
// Thread: (jq = t&127, kg = (t>>7)&1 -> 8 k's, bg = t>>8 -> 4 b's).
// kg-halves combined in smem before a single red per (b, j-quad).
__global__ void k2_vsum(const float* __restrict__ wv, const float* __restrict__ bv) {
    __shared__ float4 sw[16 * 128];   // 32 KB
    __shared__ float4 sc[256 * 4];    // 16 KB; first 512 B doubles as xs
    float* xs = reinterpret_cast<float*>(sc);

    int t = threadIdx.x;
    int jb = blockIdx.x, kc = blockIdx.y;
    int k0 = kc * 16;

    const float4* w4 = reinterpret_cast<const float4*>(wv);
#pragma unroll
    for (int u = 0; u < 4; ++u) {
        int g = t + u * 512;              // 0..2047
        int kk = g >> 7, jq = g & 127;
        sw[g] = w4[(size_t)(k0 + kk) * (HD / 4) + jb * 128 + jq];
    }
    if (t < 128) {                        // xs[b*16+kk] = merged xsum chunk
        int b = t >> 4, kk = t & 15;
        int a = b * DD + k0 + kk;
        xs[t] = g_xsum2[0][a] + g_xsum2[1][a];
    }
    __syncthreads();

    int jq = t & 127, kg = (t >> 7) & 1, bg = t >> 8;
    float4 acc[4];
#pragma unroll
    for (int i = 0; i < 4; ++i) acc[i] = make_float4(0.f, 0.f, 0.f, 0.f);
#pragma unroll
    for (int kk = 0; kk < 8; ++kk) {
        float4 wq = sw[(kg * 8 + kk) * 128 + jq];
#pragma unroll
        for (int bi = 0; bi < 4; ++bi) {
            float xv = xs[(bg * 4 + bi) * 16 + kg * 8 + kk];
            acc[bi].x += xv * wq.x; acc[bi].y += xv * wq.y;
            acc[bi].z += xv * wq.z; acc[bi].w += xv * wq.w;
        }
    }
    __syncthreads();                      // xs lifetime ends; sc begins
    int slot = (bg * 128 + jq) * 4;
    if (kg == 1) {
#pragma unroll
        for (int bi = 0; bi < 4; ++bi) sc[slot + bi] = acc[bi];
    }
    __syncthreads();
    if (kg == 0) {
        float4 lb = make_float4(0.f, 0.f, 0.f, 0.f);
        if (kc == 0) {
            float4 bv4 = reinterpret_cast<const float4*>(bv)[jb * 128 + jq];
            lb.x = 1024.f * bv4.x; lb.y = 1024.f * bv4.y;
            lb.z = 1024.f * bv4.z; lb.w = 1024.f * bv4.w;
        }
        float* base = &g_vsum4[kc & 3][0];
#pragma unroll
        for (int bi = 0; bi < 4; ++bi) {
            float4 o = sc[slot + bi];
            o.x += acc[bi].x + lb.x; o.y += acc[bi].y + lb.y;
            o.z += acc[bi].z + lb.z; o.w += acc[bi].w + lb.w;
            red_add_v4(base + (bg * 4 + bi) * HD + jb * 512 + 4 * jq, o);
        }
    }
}

// k3: zc += vsum @ fc_w (+ fc_b on jc==0).  fc_w is [HD x DD] row-major.
// grid 256 (j-chunks of 16), 512 threads. Tile: 16 j-rows x 512 i (32 KB).
// Thread: (iq = t&127, jg = (t>>7)&1 -> 8 j's, bg = t>>8 -> 4 b's).
__global__ void k3_z(const float* __restrict__ fcw, const float* __restrict__ fcb) {
    __shared__ float4 sw[16 * 128];   // 32 KB
    __shared__ float4 sc[256 * 4];    // 16 KB; first 512 B doubles as vs
    float* vs = reinterpret_cast<float*>(sc);

    int t = threadIdx.x;
    int jc = blockIdx.x;
    int j0 = jc * 16;

    const float4* w4 = reinterpret_cast<const float4*>(fcw);
#pragma unroll
    for (int u = 0; u < 4; ++u) {
        int g = t + u * 512;
        int jj = g >> 7, iq = g & 127;
        sw[g] = w4[(size_t)(j0 + jj) * (DD / 4) + iq];
    }
    if (t < 128) {                        // vs[b*16+jj] = merged vsum chunk
        int b = t >> 4, jj = t & 15;
        int a = b * HD + j0 + jj;
        vs[t] = g_vsum4[0][a] + g_vsum4[1][a] + g_vsum4[2][a] + g_vsum4[3][a];
    }
    __syncthreads();

    int iq = t & 127, jg = (t >> 7) & 1, bg = t >> 8;
    float4 acc[4];
#pragma unroll
    for (int i = 0; i < 4; ++i) acc[i] = make_float4(0.f, 0.f, 0.f, 0.f);
#pragma unroll
    for (int jj = 0; jj < 8; ++jj) {
        float4 wq = sw[(jg * 8 + jj) * 128 + iq];
#pragma unroll
        for (int bi = 0; bi < 4; ++bi) {
            float vv = vs[(bg * 4 + bi) * 16 + jg * 8 + jj];
            acc[bi].x += vv * wq.x; acc[bi].y += vv * wq.y;
            acc[bi].z += vv * wq.z; acc[bi].w += vv * wq.w;
        }
    }
    __syncthreads();
    int slot = (bg * 128 + iq) * 4;
    if (jg == 1) {
#pragma unroll
        for (int bi = 0; bi < 4; ++bi) sc[slot + bi] = acc[bi];
    }
    __syncthreads();
    if (jg == 0) {
        float4 fb = make_float4(0.f, 0.f, 0.f, 0.f);
        if (jc == 0) fb = reinterpret_cast<const float4*>(fcb)[iq];
        float* base = &g_zc[jc & 7][0];
#pragma unroll
        for (int bi = 0; bi < 4; ++bi) {
            float4 o = sc[slot + bi];
            o.x += acc[bi].x + fb.x; o.y += acc[bi].y + fb.y;
            o.z += acc[bi].z + fb.z; o.w += acc[bi].w + fb.w;
            red_add_v4(base + (bg * 4 + bi) * DD + 4 * iq, o);
        }
    }
}

// k4: out = LayerNorm(merge(zc)[b] + x[b,l]) * g + beta; warp-per-row.
// Epilogue: zero xsum2 and vsum4 for the next replay (k4 never reads them).
__global__ void k4_ln(const float* __restrict__ x,
                      const float* __restrict__ lng, const float* __restrict__ lnb,
                      float* __restrict__ out) {
    __shared__ float4 zs[128];
    int t = threadIdx.x, blk = blockIdx.x;
    int b = blk >> 7;                      // 128 blocks per batch

    if (t < 128) {
        float4 s = make_float4(0.f, 0.f, 0.f, 0.f);
#pragma unroll
        for (int c = 0; c < 8; ++c) {
            float4 v = reinterpret_cast<const float4*>(&g_zc[c][0])[b * 128 + t];
            s.x += v.x; s.y += v.y; s.z += v.z; s.w += v.w;
        }
        zs[t] = s;
    }
    __syncthreads();

    int warp = t >> 5, lane = t & 31;
    int row = blk * 8 + warp;

    const float4* xp = reinterpret_cast<const float4*>(x) + (size_t)row * 128;
    float4 y[4];
    float s = 0.f, q = 0.f;
#pragma unroll
    for (int i = 0; i < 4; ++i) {
        float4 xv = xp[lane + 32 * i];
        float4 zv = zs[lane + 32 * i];
        y[i].x = xv.x + zv.x; y[i].y = xv.y + zv.y;
        y[i].z = xv.z + zv.z; y[i].w = xv.w + zv.w;
        s += y[i].x + y[i].y + y[i].z + y[i].w;
        q += y[i].x * y[i].x + y[i].y * y[i].y + y[i].z * y[i].z + y[i].w * y[i].w;
    }
#pragma unroll
    for (int o = 16; o > 0; o >>= 1) {
        s += __shfl_xor_sync(0xFFFFFFFFu, s, o);
        q += __shfl_xor_sync(0xFFFFFFFFu, q, o);
    }
    float mu  = s * (1.0f / DD);
    float var = q * (1.0f / DD) - mu * mu;
    float inv = rsqrtf(var + 1e-5f);

    const float4* gp = reinterpret_cast<const float4*>(lng);
    const float4* bp = reinterpret_cast<const float4*>(lnb);
    float4* op = reinterpret_cast<float4*>(out) + (size_t)row * 128;
#pragma unroll
    for (int i = 0; i < 4; ++i) {
        float4 gv = gp[lane + 32 * i];
        float4 be = bp[lane + 32 * i];
        float4 o;
        o.x = (y[i].x - mu) * inv * gv.x + be.x;
        o.y = (y[i].y - mu) * inv * gv.y + be.y;
        o.z = (y[i].z - mu) * inv * gv.z + be.z;
        o.w = (y[i].w - mu) * inv * gv.w + be.w;
        op[lane + 32 * i] = o;
    }

    // Epilogue resets (safe: k4 reads neither buffer; next replay needs zeros).
    float4 z4 = make_float4(0.f, 0.f, 0.f, 0.f);
    if (t < 32)
        reinterpret_cast<float4*>(&g_vsum4[0][0])[blk * 32 + t] = z4;   // 32768 quads
    if (t < 2)
        reinterpret_cast<float4*>(&g_xsum2[0][0])[blk * 2 + t] = z4;    // 2048 quads
}

extern "C" void kernel_launch(void* const* d_in, const int* in_sizes, int n_in,
                              void* d_out, int out_size) {
    const float* input = (const float*)d_in[0];
    const float* wv    = (const float*)d_in[5];
    const float* bv    = (const float*)d_in[6];
    const float* fcw   = (const float*)d_in[9];
    const float* fcb   = (const float*)d_in[10];
    const float* lng   = (const float*)d_in[11];
    const float* lnb   = (const float*)d_in[12];
    float* out = (float*)d_out;

    kA     <<<288, 256>>>(input);
    k2_vsum<<<dim3(8, 32), 512>>>(wv, bv);
    k3_z   <<<256, 512>>>(fcw, fcb);
    k4_ln  <<<1024, 256>>>(input, lng, lnb, out);
}

// round 6
// speedup vs baseline: 1.4887x; 1.0633x over previous
#include <cuda_runtime.h>

#define BB 8
#define LL 1024
#define DD 512
#define HD 4096

// Accumulators. Zero at module load (first call OK); k4's epilogue re-zeroes
// xsum2/vsum4 for the next replay; zc re-zeroed by kA's extra blocks each call.
__device__ __align__(16) float g_xsum2[2][BB * DD];   // 32 KB
__device__ __align__(16) float g_vsum4[4][BB * HD];   // 512 KB
__device__ __align__(16) float g_zc[8][BB * DD];      // 128 KB

__device__ __forceinline__ void red_add_v4(float* a, float4 v) {
    asm volatile("red.global.add.v4.f32 [%0], {%1,%2,%3,%4};"
                 :: "l"(a), "f"(v.x), "f"(v.y), "f"(v.z), "f"(v.w) : "memory");
}

// kA: blocks [0,512): xsum += input over 16-row chunks (red into 2 copies).
//     blocks [512,544): zero g_zc for this call.
__global__ __launch_bounds__(256) void kA(const float* __restrict__ x) {
    int blk = blockIdx.x, t = threadIdx.x;
    if (blk >= 512) {
        int q = (blk - 512) * 256 + t;   // 8192 quads
        reinterpret_cast<float4*>(&g_zc[0][0])[q] = make_float4(0.f, 0.f, 0.f, 0.f);
        return;
    }
    int b = blk >> 6, c = blk & 63;          // 64 L-chunks of 16 rows
    int h = t >> 7, q = t & 127;             // 8-row half, quad
    const float4* p = reinterpret_cast<const float4*>(x)
                    + (size_t)b * LL * 128 + (size_t)(c * 16 + h * 8) * 128 + q;
    float4 s = make_float4(0.f, 0.f, 0.f, 0.f);
#pragma unroll
    for (int r = 0; r < 8; ++r) {
        float4 v = p[r * 128];
        s.x += v.x; s.y += v.y; s.z += v.z; s.w += v.w;
    }
    red_add_v4(&g_xsum2[h][b * DD + 4 * q], s);
}

// k2: vsum += xsum @ wv (+ L*bv on kc==0).  wv is [DD x HD] row-major.
// grid (jb=8, kc=32), 512 threads; 32 KB tile; in-block kg-half combine.
__global__ void k2_vsum(const float* __restrict__ wv, const float* __restrict__ bv) {
    __shared__ float4 sw[16 * 128];   // 32 KB
    __shared__ float4 sc[256 * 4];    // 16 KB; first 512 B doubles as xs
    float* xs = reinterpret_cast<float*>(sc);

    int t = threadIdx.x;
    int jb = blockIdx.x, kc = blockIdx.y;
    int k0 = kc * 16;

    const float4* w4 = reinterpret_cast<const float4*>(wv);
#pragma unroll
    for (int u = 0; u < 4; ++u) {
        int g = t + u * 512;
        int kk = g >> 7, jq = g & 127;
        sw[g] = w4[(size_t)(k0 + kk) * (HD / 4) + jb * 128 + jq];
    }
    if (t < 128) {
        int b = t >> 4, kk = t & 15;
        int a = b * DD + k0 + kk;
        xs[t] = g_xsum2[0][a] + g_xsum2[1][a];
    }
    __syncthreads();

    int jq = t & 127, kg = (t >> 7) & 1, bg = t >> 8;
    float4 acc[4];
#pragma unroll
    for (int i = 0; i < 4; ++i) acc[i] = make_float4(0.f, 0.f, 0.f, 0.f);
#pragma unroll
    for (int kk = 0; kk < 8; ++kk) {
        float4 wq = sw[(kg * 8 + kk) * 128 + jq];
#pragma unroll
        for (int bi = 0; bi < 4; ++bi) {
            float xv = xs[(bg * 4 + bi) * 16 + kg * 8 + kk];
            acc[bi].x += xv * wq.x; acc[bi].y += xv * wq.y;
            acc[bi].z += xv * wq.z; acc[bi].w += xv * wq.w;
        }
    }
    __syncthreads();
    int slot = (bg * 128 + jq) * 4;
    if (kg == 1) {
#pragma unroll
        for (int bi = 0; bi < 4; ++bi) sc[slot + bi] = acc[bi];
    }
    __syncthreads();
    if (kg == 0) {
        float4 lb = make_float4(0.f, 0.f, 0.f, 0.f);
        if (kc == 0) {
            float4 bv4 = reinterpret_cast<const float4*>(bv)[jb * 128 + jq];
            lb.x = 1024.f * bv4.x; lb.y = 1024.f * bv4.y;
            lb.z = 1024.f * bv4.z; lb.w = 1024.f * bv4.w;
        }
        float* base = &g_vsum4[kc & 3][0];
#pragma unroll
        for (int bi = 0; bi < 4; ++bi) {
            float4 o = sc[slot + bi];
            o.x += acc[bi].x + lb.x; o.y += acc[bi].y + lb.y;
            o.z += acc[bi].z + lb.z; o.w += acc[bi].w + lb.w;
            red_add_v4(base + (bg * 4 + bi) * HD + jb * 512 + 4 * jq, o);
        }
    }
}

// k3: zc += vsum @ fc_w (+ fc_b on jc==0).  fc_w is [HD x DD] row-major.
// grid 256 (j-chunks of 16), 512 threads; 32 KB tile; jg-half combine.
__global__ void k3_z(const float* __restrict__ fcw, const float* __restrict__ fcb) {
    __shared__ float4 sw[16 * 128];
    __shared__ float4 sc[256 * 4];
    float* vs = reinterpret_cast<float*>(sc);

    int t = threadIdx.x;
    int jc = blockIdx.x;
    int j0 = jc * 16;

    const float4* w4 = reinterpret_cast<const float4*>(fcw);
#pragma unroll
    for (int u = 0; u < 4; ++u) {
        int g = t + u * 512;
        int jj = g >> 7, iq = g & 127;
        sw[g] = w4[(size_t)(j0 + jj) * (DD / 4) + iq];
    }
    if (t < 128) {
        int b = t >> 4, jj = t & 15;
        int a = b * HD + j0 + jj;
        vs[t] = g_vsum4[0][a] + g_vsum4[1][a] + g_vsum4[2][a] + g_vsum4[3][a];
    }
    __syncthreads();

    int iq = t & 127, jg = (t >> 7) & 1, bg = t >> 8;
    float4 acc[4];
#pragma unroll
    for (int i = 0; i < 4; ++i) acc[i] = make_float4(0.f, 0.f, 0.f, 0.f);
#pragma unroll
    for (int jj = 0; jj < 8; ++jj) {
        float4 wq = sw[(jg * 8 + jj) * 128 + iq];
#pragma unroll
        for (int bi = 0; bi < 4; ++bi) {
            float vv = vs[(bg * 4 + bi) * 16 + jg * 8 + jj];
            acc[bi].x += vv * wq.x; acc[bi].y += vv * wq.y;
            acc[bi].z += vv * wq.z; acc[bi].w += vv * wq.w;
        }
    }
    __syncthreads();
    int slot = (bg * 128 + iq) * 4;
    if (jg == 1) {
#pragma unroll
        for (int bi = 0; bi < 4; ++bi) sc[slot + bi] = acc[bi];
    }
    __syncthreads();
    if (jg == 0) {
        float4 fb = make_float4(0.f, 0.f, 0.f, 0.f);
        if (jc == 0) fb = reinterpret_cast<const float4*>(fcb)[iq];
        float* base = &g_zc[jc & 7][0];
#pragma unroll
        for (int bi = 0; bi < 4; ++bi) {
            float4 o = sc[slot + bi];
            o.x += acc[bi].x + fb.x; o.y += acc[bi].y + fb.y;
            o.z += acc[bi].z + fb.z; o.w += acc[bi].w + fb.w;
            red_add_v4(base + (bg * 4 + bi) * DD + 4 * iq, o);
        }
    }
}

// k4: out = LayerNorm(merge(zc)[b] + x[b,l]) * g + beta.
// 512 blocks x 256 threads; each warp handles TWO rows, loads pipelined
// (8 independent LDG.128 before any reduce), 4 parallel shuffle chains.
// Epilogue zeroes xsum2/vsum4 for the next replay.
__global__ __launch_bounds__(256, 4) void k4_ln(
        const float* __restrict__ x,
        const float* __restrict__ lng, const float* __restrict__ lnb,
        float* __restrict__ out) {
    __shared__ float4 zs[128];
    int t = threadIdx.x, blk = blockIdx.x;
    int b = blk >> 6;                      // 64 blocks (16 rows each) per batch

    if (t < 128) {
        float4 s = make_float4(0.f, 0.f, 0.f, 0.f);
#pragma unroll
        for (int c = 0; c < 8; ++c) {
            float4 v = reinterpret_cast<const float4*>(&g_zc[c][0])[b * 128 + t];
            s.x += v.x; s.y += v.y; s.z += v.z; s.w += v.w;
        }
        zs[t] = s;
    }
    __syncthreads();

    int warp = t >> 5, lane = t & 31;
    int row0 = blk * 16 + warp * 2;

    const float4* xp0 = reinterpret_cast<const float4*>(x) + (size_t)row0 * 128;
    const float4* xp1 = xp0 + 128;

    float4 xa[4], xb[4];
#pragma unroll
    for (int i = 0; i < 4; ++i) xa[i] = xp0[lane + 32 * i];
#pragma unroll
    for (int i = 0; i < 4; ++i) xb[i] = xp1[lane + 32 * i];

    float sa = 0.f, qa = 0.f, sb = 0.f, qb = 0.f;
#pragma unroll
    for (int i = 0; i < 4; ++i) {
        float4 z = zs[lane + 32 * i];
        float y;
        y = xa[i].x + z.x; sa += y; qa += y * y;
        y = xa[i].y + z.y; sa += y; qa += y * y;
        y = xa[i].z + z.z; sa += y; qa += y * y;
        y = xa[i].w + z.w; sa += y; qa += y * y;
        y = xb[i].x + z.x; sb += y; qb += y * y;
        y = xb[i].y + z.y; sb += y; qb += y * y;
        y = xb[i].z + z.z; sb += y; qb += y * y;
        y = xb[i].w + z.w; sb += y; qb += y * y;
    }
#pragma unroll
    for (int o = 16; o > 0; o >>= 1) {
        sa += __shfl_xor_sync(0xFFFFFFFFu, sa, o);
        qa += __shfl_xor_sync(0xFFFFFFFFu, qa, o);
        sb += __shfl_xor_sync(0xFFFFFFFFu, sb, o);
        qb += __shfl_xor_sync(0xFFFFFFFFu, qb, o);
    }
    float mua  = sa * (1.0f / DD);
    float inva = rsqrtf(qa * (1.0f / DD) - mua * mua + 1e-5f);
    float mub  = sb * (1.0f / DD);
    float invb = rsqrtf(qb * (1.0f / DD) - mub * mub + 1e-5f);

    const float4* gp = reinterpret_cast<const float4*>(lng);
    const float4* bp = reinterpret_cast<const float4*>(lnb);
    float4* op0 = reinterpret_cast<float4*>(out) + (size_t)row0 * 128;
    float4* op1 = op0 + 128;
#pragma unroll
    for (int i = 0; i < 4; ++i) {
        float4 z  = zs[lane + 32 * i];
        float4 gv = gp[lane + 32 * i];
        float4 be = bp[lane + 32 * i];
        float4 o;
        o.x = (xa[i].x + z.x - mua) * inva * gv.x + be.x;
        o.y = (xa[i].y + z.y - mua) * inva * gv.y + be.y;
        o.z = (xa[i].z + z.z - mua) * inva * gv.z + be.z;
        o.w = (xa[i].w + z.w - mua) * inva * gv.w + be.w;
        op0[lane + 32 * i] = o;
        o.x = (xb[i].x + z.x - mub) * invb * gv.x + be.x;
        o.y = (xb[i].y + z.y - mub) * invb * gv.y + be.y;
        o.z = (xb[i].z + z.z - mub) * invb * gv.z + be.z;
        o.w = (xb[i].w + z.w - mub) * invb * gv.w + be.w;
        op1[lane + 32 * i] = o;
    }

    // Epilogue resets for next replay (k4 reads neither buffer).
    float4 z4 = make_float4(0.f, 0.f, 0.f, 0.f);
    if (t < 64)
        reinterpret_cast<float4*>(&g_vsum4[0][0])[blk * 64 + t] = z4;   // 32768 quads
    if (t < 4)
        reinterpret_cast<float4*>(&g_xsum2[0][0])[blk * 4 + t] = z4;    // 2048 quads
}

extern "C" void kernel_launch(void* const* d_in, const int* in_sizes, int n_in,
                              void* d_out, int out_size) {
    const float* input = (const float*)d_in[0];
    const float* wv    = (const float*)d_in[5];
    const float* bv    = (const float*)d_in[6];
    const float* fcw   = (const float*)d_in[9];
    const float* fcb   = (const float*)d_in[10];
    const float* lng   = (const float*)d_in[11];
    const float* lnb   = (const float*)d_in[12];
    float* out = (float*)d_out;

    kA     <<<544, 256>>>(input);
    k2_vsum<<<dim3(8, 32), 512>>>(wv, bv);
    k3_z   <<<256, 512>>>(fcw, fcb);
    k4_ln  <<<512, 256>>>(input, lng, lnb, out);
}